// round 2
// baseline (speedup 1.0000x reference)
#include <cuda_runtime.h>
#include <cuda_bf16.h>

#define NC 35
#define TPB 256

__global__ void fll_zero_kernel(float* out) { *out = 0.0f; }

__global__ __launch_bounds__(TPB) void fll_loss_kernel(
    const float* __restrict__ logits,
    const int* __restrict__ targets,
    const int* __restrict__ turns,
    float* __restrict__ out,
    int B, float invB)
{
    __shared__ float sm[TPB * NC];   // 35840 B

    const int block_row0 = blockIdx.x * TPB;
    const int rows = min(TPB, B - block_row0);

    // ---- cooperative staged load: global -> smem ----
    if (rows == TPB) {
        // region is 16B aligned: 256*35*4 = 35840 B per block
        const float4* __restrict__ src =
            (const float4*)(logits + (size_t)block_row0 * NC);
        float4* dst = (float4*)sm;
        const int total4 = TPB * NC / 4;   // 2240
        #pragma unroll
        for (int i = threadIdx.x; i < total4; i += TPB) dst[i] = src[i];
    } else {
        const float* __restrict__ src = logits + (size_t)block_row0 * NC;
        const int total = rows * NC;
        for (int i = threadIdx.x; i < total; i += TPB) sm[i] = src[i];
    }
    __syncthreads();

    // ---- per-thread row softmax cross-entropy ----
    float acc = 0.0f;
    const int r = threadIdx.x;
    if (r < rows) {
        const float* row = sm + r * NC;   // lane stride 35 words: conflict-free
        float v[NC];
        #pragma unroll
        for (int c = 0; c < NC; c++) v[c] = row[c];

        // max with 4-way ILP
        float m0 = v[0], m1 = v[1], m2 = v[2], m3 = v[3];
        #pragma unroll
        for (int c = 4; c < NC; c += 4) {
            m0 = fmaxf(m0, v[c]);
            if (c + 1 < NC) m1 = fmaxf(m1, v[c + 1]);
            if (c + 2 < NC) m2 = fmaxf(m2, v[c + 2]);
            if (c + 3 < NC) m3 = fmaxf(m3, v[c + 3]);
        }
        const float mx = fmaxf(fmaxf(m0, m1), fmaxf(m2, m3));

        // sum of exp with 4 accumulators
        float s0 = 0.f, s1 = 0.f, s2 = 0.f, s3 = 0.f;
        #pragma unroll
        for (int c = 0; c < NC; c += 4) {
            s0 += __expf(v[c] - mx);
            if (c + 1 < NC) s1 += __expf(v[c + 1] - mx);
            if (c + 2 < NC) s2 += __expf(v[c + 2] - mx);
            if (c + 3 < NC) s3 += __expf(v[c + 3] - mx);
        }
        const float s = (s0 + s1) + (s2 + s3);

        const int gi = block_row0 + r;
        const int tgt = targets[gi];
        const float xt = row[tgt];                // dynamic index -> smem read
        const float loss = __logf(s) + mx - xt;

        const float t = (float)turns[gi];
        const float w = fminf(fmaxf(0.7f + 0.05f * (t - 6.0f), 0.7f), 1.0f);
        acc = w * loss;
    }

    // ---- block reduction ----
    #pragma unroll
    for (int o = 16; o > 0; o >>= 1)
        acc += __shfl_down_sync(0xffffffffu, acc, o);

    __shared__ float wsum[TPB / 32];
    if ((threadIdx.x & 31) == 0) wsum[threadIdx.x >> 5] = acc;
    __syncthreads();

    if (threadIdx.x < TPB / 32) {
        float a = wsum[threadIdx.x];
        #pragma unroll
        for (int o = TPB / 64; o > 0; o >>= 1)
            a += __shfl_down_sync(0xffu, a, o);
        if (threadIdx.x == 0) atomicAdd(out, a * invB);
    }
}

extern "C" void kernel_launch(void* const* d_in, const int* in_sizes, int n_in,
                              void* d_out, int out_size)
{
    const float* logits  = (const float*)d_in[0];
    const int*   targets = (const int*)d_in[1];
    const int*   turns   = (const int*)d_in[2];
    float* out = (float*)d_out;

    const int B = in_sizes[1];                 // element count of targets
    const int grid = (B + TPB - 1) / TPB;

    fll_zero_kernel<<<1, 1>>>(out);
    fll_loss_kernel<<<grid, TPB>>>(logits, targets, turns, out, B, 1.0f / (float)B);
}

// round 3
// speedup vs baseline: 1.0615x; 1.0615x over previous
#include <cuda_runtime.h>
#include <cuda_bf16.h>

#define NC   35
#define TPB  128
#define TILE 128

__device__ __forceinline__ void cp_async16(void* dst, const void* src) {
    unsigned s = (unsigned)__cvta_generic_to_shared(dst);
    asm volatile("cp.async.cg.shared.global [%0], [%1], 16;" :: "r"(s), "l"(src) : "memory");
}
__device__ __forceinline__ void cp_async4(void* dst, const void* src) {
    unsigned s = (unsigned)__cvta_generic_to_shared(dst);
    asm volatile("cp.async.ca.shared.global [%0], [%1], 4;" :: "r"(s), "l"(src) : "memory");
}
#define CP_COMMIT()  asm volatile("cp.async.commit_group;" ::: "memory")
#define CP_WAIT(n)   asm volatile("cp.async.wait_group %0;" :: "n"(n) : "memory")

__global__ void fll_zero_kernel(float* out) { *out = 0.0f; }

__global__ __launch_bounds__(TPB) void fll_loss_kernel(
    const float* __restrict__ logits,
    const int* __restrict__ targets,
    const int* __restrict__ turns,
    float* __restrict__ out,
    int B, float invB)
{
    __shared__ float sl[2][TILE * NC];   // 2 x 17920 B
    __shared__ int   st[2][TILE];        // targets
    __shared__ int   su[2][TILE];        // turns

    const int tid    = threadIdx.x;
    const int ntiles = (B + TILE - 1) / TILE;

    // ---- prefetch helper ----
    auto prefetch = [&](int tile, int b) {
        const int row0 = tile * TILE;
        const int rows = min(TILE, B - row0);
        if (rows == TILE) {
            const float4* src = (const float4*)(logits + (size_t)row0 * NC);
            float4*       dst = (float4*)sl[b];
            #pragma unroll
            for (int i = tid; i < TILE * NC / 4; i += TPB)   // 1120 chunks
                cp_async16(dst + i, src + i);
            if (tid < TILE / 4) {
                cp_async16(((int4*)st[b]) + tid, ((const int4*)(targets + row0)) + tid);
                cp_async16(((int4*)su[b]) + tid, ((const int4*)(turns   + row0)) + tid);
            }
        } else {  // tail tile: scalar async copies
            for (int i = tid; i < rows * NC; i += TPB)
                cp_async4(&sl[b][i], logits + (size_t)row0 * NC + i);
            for (int i = tid; i < rows; i += TPB) {
                cp_async4(&st[b][i], targets + row0 + i);
                cp_async4(&su[b][i], turns   + row0 + i);
            }
        }
        CP_COMMIT();
    };

    float acc = 0.0f;
    int buf = 0;
    int tile = blockIdx.x;
    if (tile < ntiles) prefetch(tile, 0);

    for (; tile < ntiles; tile += gridDim.x, buf ^= 1) {
        const int next = tile + gridDim.x;
        if (next < ntiles) { prefetch(next, buf ^ 1); CP_WAIT(1); }
        else               { CP_WAIT(0); }
        __syncthreads();   // all threads' async data for 'buf' visible

        const int rows = min(TILE, B - tile * TILE);
        if (tid < rows) {
            const float* row = &sl[buf][tid * NC];   // stride 35: conflict-free
            float v[NC];
            #pragma unroll
            for (int c = 0; c < NC; c++) v[c] = row[c];

            float m0 = v[0], m1 = v[1], m2 = v[2], m3 = v[3];
            #pragma unroll
            for (int c = 4; c < NC; c += 4) {
                m0 = fmaxf(m0, v[c]);
                if (c + 1 < NC) m1 = fmaxf(m1, v[c + 1]);
                if (c + 2 < NC) m2 = fmaxf(m2, v[c + 2]);
                if (c + 3 < NC) m3 = fmaxf(m3, v[c + 3]);
            }
            const float mx = fmaxf(fmaxf(m0, m1), fmaxf(m2, m3));

            float s0 = 0.f, s1 = 0.f, s2 = 0.f, s3 = 0.f;
            #pragma unroll
            for (int c = 0; c < NC; c += 4) {
                s0 += __expf(v[c] - mx);
                if (c + 1 < NC) s1 += __expf(v[c + 1] - mx);
                if (c + 2 < NC) s2 += __expf(v[c + 2] - mx);
                if (c + 3 < NC) s3 += __expf(v[c + 3] - mx);
            }
            const float s = (s0 + s1) + (s2 + s3);

            const int   tgt  = st[buf][tid];
            const float xt   = row[tgt];      // dynamic index stays in smem
            const float loss = __logf(s) + mx - xt;

            const float t = (float)su[buf][tid];
            const float w = fminf(fmaxf(0.7f + 0.05f * (t - 6.0f), 0.7f), 1.0f);
            acc += w * loss;
        }
        __syncthreads();   // buffer 'buf' free before it's refilled next pass
    }

    // ---- one block reduction at the very end ----
    #pragma unroll
    for (int o = 16; o > 0; o >>= 1)
        acc += __shfl_down_sync(0xffffffffu, acc, o);

    __shared__ float wsum[TPB / 32];
    if ((tid & 31) == 0) wsum[tid >> 5] = acc;
    __syncthreads();

    if (tid < TPB / 32) {
        float a = wsum[tid];
        #pragma unroll
        for (int o = TPB / 64; o > 0; o >>= 1)
            a += __shfl_down_sync(0xfu, a, o);
        if (tid == 0) atomicAdd(out, a * invB);
    }
}

extern "C" void kernel_launch(void* const* d_in, const int* in_sizes, int n_in,
                              void* d_out, int out_size)
{
    const float* logits  = (const float*)d_in[0];
    const int*   targets = (const int*)d_in[1];
    const int*   turns   = (const int*)d_in[2];
    float* out = (float*)d_out;

    const int B      = in_sizes[1];
    const int ntiles = (B + TILE - 1) / TILE;
    int grid = 148 * 6;                 // persistent: 6 blocks/SM (smem-limited)
    if (grid > ntiles) grid = ntiles;

    fll_zero_kernel<<<1, 1>>>(out);
    fll_loss_kernel<<<grid, TPB>>>(logits, targets, turns, out, B, 1.0f / (float)B);
}

// round 4
// speedup vs baseline: 1.1897x; 1.1207x over previous
#include <cuda_runtime.h>
#include <cuda_bf16.h>

#define NC   35
#define TPB  128
#define TILE 128

__device__ unsigned g_ctr  = 0;   // next tile index
__device__ unsigned g_done = 0;   // finished-block count
__device__ float    g_acc  = 0.f; // global loss accumulator

__device__ __forceinline__ void cp_async16(void* dst, const void* src) {
    unsigned s = (unsigned)__cvta_generic_to_shared(dst);
    asm volatile("cp.async.cg.shared.global [%0], [%1], 16;" :: "r"(s), "l"(src) : "memory");
}
__device__ __forceinline__ void cp_async4(void* dst, const void* src) {
    unsigned s = (unsigned)__cvta_generic_to_shared(dst);
    asm volatile("cp.async.ca.shared.global [%0], [%1], 4;" :: "r"(s), "l"(src) : "memory");
}
#define CP_COMMIT()  asm volatile("cp.async.commit_group;" ::: "memory")
#define CP_WAIT(n)   asm volatile("cp.async.wait_group %0;" :: "n"(n) : "memory")

__global__ __launch_bounds__(TPB) void fll_loss_kernel(
    const float* __restrict__ logits,
    const int* __restrict__ targets,
    const int* __restrict__ turns,
    float* __restrict__ out,
    int B, float invB)
{
    __shared__ float sl[2][TILE * NC];   // 2 x 17920 B
    __shared__ int   st[2][TILE];
    __shared__ int   su[2][TILE];
    __shared__ int   s_next;

    const int tid    = threadIdx.x;
    const int ntiles = (B + TILE - 1) / TILE;

    auto prefetch = [&](int tile, int b) {
        const int row0 = tile * TILE;
        const int rows = min(TILE, B - row0);
        if (rows == TILE) {
            const float4* src = (const float4*)(logits + (size_t)row0 * NC);
            float4*       dst = (float4*)sl[b];
            #pragma unroll
            for (int i = tid; i < TILE * NC / 4; i += TPB)    // 1120 x 16B
                cp_async16(dst + i, src + i);
            if (tid < TILE / 4) {
                cp_async16(((int4*)st[b]) + tid, ((const int4*)(targets + row0)) + tid);
                cp_async16(((int4*)su[b]) + tid, ((const int4*)(turns   + row0)) + tid);
            }
        } else {   // tail tile
            for (int i = tid; i < rows * NC; i += TPB)
                cp_async4(&sl[b][i], logits + (size_t)row0 * NC + i);
            for (int i = tid; i < rows; i += TPB) {
                cp_async4(&st[b][i], targets + row0 + i);
                cp_async4(&su[b][i], turns   + row0 + i);
            }
        }
        CP_COMMIT();
    };

    // ---- grab first tile dynamically ----
    if (tid == 0) s_next = (int)atomicAdd(&g_ctr, 1u);
    __syncthreads();
    int cur = s_next;
    int buf = 0;
    float acc = 0.0f;
    if (cur < ntiles) prefetch(cur, 0);

    while (cur < ntiles) {
        if (tid == 0) s_next = (int)atomicAdd(&g_ctr, 1u);
        __syncthreads();                       // all compute on buf^1 done; s_next visible
        const int next = s_next;
        if (next < ntiles) { prefetch(next, buf ^ 1); CP_WAIT(1); }
        else               { CP_WAIT(0); }
        __syncthreads();                       // buf data landed for all threads

        const int rows = min(TILE, B - cur * TILE);
        if (tid < rows) {
            const float* row = &sl[buf][tid * NC];   // stride 35: conflict-free
            float v[NC];
            #pragma unroll
            for (int c = 0; c < NC; c++) v[c] = row[c];

            float m0 = v[0], m1 = v[1], m2 = v[2], m3 = v[3];
            #pragma unroll
            for (int c = 4; c < NC; c += 4) {
                m0 = fmaxf(m0, v[c]);
                if (c + 1 < NC) m1 = fmaxf(m1, v[c + 1]);
                if (c + 2 < NC) m2 = fmaxf(m2, v[c + 2]);
                if (c + 3 < NC) m3 = fmaxf(m3, v[c + 3]);
            }
            const float mx = fmaxf(fmaxf(m0, m1), fmaxf(m2, m3));

            float s0 = 0.f, s1 = 0.f, s2 = 0.f, s3 = 0.f;
            #pragma unroll
            for (int c = 0; c < NC; c += 4) {
                s0 += __expf(v[c] - mx);
                if (c + 1 < NC) s1 += __expf(v[c + 1] - mx);
                if (c + 2 < NC) s2 += __expf(v[c + 2] - mx);
                if (c + 3 < NC) s3 += __expf(v[c + 3] - mx);
            }
            const float s = (s0 + s1) + (s2 + s3);

            const int   tgt  = st[buf][tid];
            const float xt   = row[tgt];
            const float loss = __logf(s) + mx - xt;

            const float t = (float)su[buf][tid];
            const float w = fminf(fmaxf(0.7f + 0.05f * (t - 6.0f), 0.7f), 1.0f);
            acc += w * loss;
        }
        cur = next;
        buf ^= 1;
    }

    // ---- block reduction ----
    #pragma unroll
    for (int o = 16; o > 0; o >>= 1)
        acc += __shfl_down_sync(0xffffffffu, acc, o);

    __shared__ float wsum[TPB / 32];
    if ((tid & 31) == 0) wsum[tid >> 5] = acc;
    __syncthreads();

    if (tid == 0) {
        float a = wsum[0];
        #pragma unroll
        for (int wgi = 1; wgi < TPB / 32; wgi++) a += wsum[wgi];

        atomicAdd(&g_acc, a);
        __threadfence();
        const unsigned prev = atomicAdd(&g_done, 1u);
        if (prev == gridDim.x - 1) {
            // last block out: every other block's g_acc add is fenced-visible
            const float total = atomicExch(&g_acc, 0.0f);
            *out = total * invB;
            g_ctr  = 0;           // self-clean for graph replay
            g_done = 0;
            __threadfence();
        }
    }
}

extern "C" void kernel_launch(void* const* d_in, const int* in_sizes, int n_in,
                              void* d_out, int out_size)
{
    const float* logits  = (const float*)d_in[0];
    const int*   targets = (const int*)d_in[1];
    const int*   turns   = (const int*)d_in[2];
    float* out = (float*)d_out;

    const int B      = in_sizes[1];
    const int ntiles = (B + TILE - 1) / TILE;
    int grid = 148 * 6;                // persistent, smem-limited occupancy
    if (grid > ntiles) grid = ntiles;

    fll_loss_kernel<<<grid, TPB>>>(logits, targets, turns, out, B, 1.0f / (float)B);
}